// round 15
// baseline (speedup 1.0000x reference)
#include <cuda_runtime.h>
#include <cstdint>
#include <cstddef>

#define T_STEPS 256
#define BATCH   64
#define DIN     512
#define R       2048
#define DOUT    128
#define NW      (R*R)            // 4194304
#define KEEPK   838860u          // max(1, int(NW * (1-0.8)))
#define BETA    0.9f
#define NCH     16               // row chunks — matches round-0 KS for bitwise identity
#define CHR     (R/NCH)          // 128 rows per chunk
#define MAXNZ   64               // capacity per (chunk, col); mean 25.6
#define SSTRIDE 20               // padded u16 row stride (40B) -> spread LDS.64 banks
#define NBLK    1024             // persistent scan grid (co-resident: 7/SM x 148 = 1036)

// ---------------- device scratch (static, no allocation) ----------------
__device__ float      g_drive[(size_t)T_STEPS*BATCH*R];             // 128 MB
__device__ float      g_part [(size_t)NCH*BATCH*R];                 // 8 MB
__device__ float      g_V    [BATCH*R];
__device__ unsigned short g_St16[R*BATCH];                          // spikes as f32-high-half u16, [i][b]
__device__ uint2      g_ent  [(size_t)NCH*MAXNZ*R];                 // {w_bits, row} 16 MB
__device__ int        g_cnt  [NCH*R];
__device__ unsigned   g_bits [(size_t)T_STEPS*BATCH*(R/32)];        // 4 MB spike bitmasks
__device__ unsigned   g_hist1[65536];
__device__ unsigned   g_hist2[65536];
__device__ unsigned   g_bucket;
__device__ unsigned   g_krem;
__device__ unsigned   g_cntabove;
__device__ float      g_thresh;
__device__ float      g_active_ratio;
__device__ unsigned long long g_spk;
__device__ unsigned   g_barcnt;

// ---------------- threshold selection (exact, 2-pass radix) ----------------
__global__ void hist1_k(const float* __restrict__ w) {
    unsigned i = blockIdx.x * blockDim.x + threadIdx.x;
    unsigned stride = gridDim.x * blockDim.x;
    for (; i < NW; i += stride) {
        unsigned key = __float_as_uint(w[i]) & 0x7fffffffu;
        atomicAdd(&g_hist1[key >> 16], 1u);
    }
}

__global__ void sel1_k() {
    __shared__ unsigned ssum[1024];
    int t = threadIdx.x;
    unsigned s = 0;
    for (int j = 0; j < 64; j++) s += g_hist1[t*64 + j];
    ssum[t] = s;
    __syncthreads();
    if (t == 0) {
        unsigned long long cum = 0;
        int c = 1023;
        for (; c >= 0; c--) {
            if (cum + ssum[c] >= (unsigned long long)KEEPK) break;
            cum += ssum[c];
        }
        unsigned bucket = 0;
        for (int j = 63; j >= 0; j--) {
            unsigned h = g_hist1[c*64 + j];
            if (cum + h >= (unsigned long long)KEEPK) { bucket = (unsigned)(c*64 + j); break; }
            cum += h;
        }
        g_bucket   = bucket;
        g_cntabove = (unsigned)cum;
        g_krem     = KEEPK - (unsigned)cum;
    }
}

__global__ void hist2_k(const float* __restrict__ w) {
    unsigned bucket = g_bucket;
    unsigned i = blockIdx.x * blockDim.x + threadIdx.x;
    unsigned stride = gridDim.x * blockDim.x;
    for (; i < NW; i += stride) {
        unsigned key = __float_as_uint(w[i]) & 0x7fffffffu;
        if ((key >> 16) == bucket) atomicAdd(&g_hist2[key & 0xffffu], 1u);
    }
}

__global__ void sel2_k() {
    __shared__ unsigned ssum[1024];
    int t = threadIdx.x;
    unsigned s = 0;
    for (int j = 0; j < 64; j++) s += g_hist2[t*64 + j];
    ssum[t] = s;
    __syncthreads();
    if (t == 0) {
        unsigned krem = g_krem;
        unsigned long long cum = 0;
        int c = 1023;
        for (; c >= 0; c--) {
            if (cum + ssum[c] >= (unsigned long long)krem) break;
            cum += ssum[c];
        }
        unsigned low = 0;
        for (int j = 63; j >= 0; j--) {
            unsigned h = g_hist2[c*64 + j];
            cum += h;
            if (cum >= (unsigned long long)krem) { low = (unsigned)(c*64 + j); break; }
        }
        unsigned bits = (g_bucket << 16) | low;
        g_thresh = __uint_as_float(bits);
        unsigned long long cnt_ge = (unsigned long long)g_cntabove + cum;
        g_active_ratio = (float)((double)cnt_ge / (double)NW);
    }
}

// ---------------- build padded column-compressed W_eff ----------------
__global__ void __launch_bounds__(128) build_k(const float* __restrict__ w) {
    int idx = blockIdx.x * 128 + threadIdx.x;       // 0 .. NCH*R-1
    if (idx >= NCH * R) return;
    int chunk = idx >> 11;
    int col   = idx & (R - 1);
    float th = g_thresh;
    int cnt = 0;
    #pragma unroll 4
    for (int r = 0; r < CHR; r++) {
        float v = w[(size_t)(chunk * CHR + r) * R + col];
        if (fabsf(v) >= th && cnt < MAXNZ) {
            g_ent[((size_t)chunk * MAXNZ + cnt) * R + col] =
                make_uint2(__float_as_uint(v), (unsigned)r);
            cnt++;
        }
    }
    g_cnt[idx] = cnt;
}

// ---------------- input projection: drive = x @ w_in + b_in ----------------
// 128x128 tile, 256 threads, 8x8 per thread. Per-element chain over k is
// ascending — bitwise identical to the previous tiling.
#define BM2 128
#define BN2 128
#define BK2 8
__global__ void __launch_bounds__(256) drive_k(const float* __restrict__ A,
                                               const float* __restrict__ Bw,
                                               const float* __restrict__ bias) {
    __shared__ __align__(16) float sA[BK2][BM2];
    __shared__ __align__(16) float sB[BK2][BN2];
    int bm = blockIdx.y * BM2;
    int bn = blockIdx.x * BN2;
    int tid = threadIdx.x;
    int tx = tid & 15, ty = tid >> 4;
    float acc[8][8] = {};
    for (int k0 = 0; k0 < DIN; k0 += BK2) {
        #pragma unroll
        for (int e = 0; e < 4; e++) {
            int idx = tid + e * 256;
            int m = idx >> 3, k = idx & 7;
            sA[k][m] = A[(size_t)(bm + m) * DIN + k0 + k];
        }
        #pragma unroll
        for (int e = 0; e < 4; e++) {
            int idx = tid + e * 256;
            int k = idx >> 7, n = idx & 127;
            sB[k][n] = Bw[(size_t)(k0 + k) * R + bn + n];
        }
        __syncthreads();
        #pragma unroll
        for (int k = 0; k < BK2; k++) {
            float a[8], b[8];
            #pragma unroll
            for (int u = 0; u < 4; u++)
                *reinterpret_cast<float4*>(&a[u & 2 ? 4 : 0]), (void)0;
            // explicit vector loads
            *reinterpret_cast<float4*>(&a[0]) = *reinterpret_cast<const float4*>(&sA[k][ty*8]);
            *reinterpret_cast<float4*>(&a[4]) = *reinterpret_cast<const float4*>(&sA[k][ty*8 + 4]);
            *reinterpret_cast<float4*>(&b[0]) = *reinterpret_cast<const float4*>(&sB[k][tx*8]);
            *reinterpret_cast<float4*>(&b[4]) = *reinterpret_cast<const float4*>(&sB[k][tx*8 + 4]);
            #pragma unroll
            for (int i = 0; i < 8; i++)
                #pragma unroll
                for (int j = 0; j < 8; j++)
                    acc[i][j] += a[i] * b[j];
        }
        __syncthreads();
    }
    #pragma unroll
    for (int i = 0; i < 8; i++)
        #pragma unroll
        for (int j = 0; j < 8; j++)
            g_drive[(size_t)(bm + ty*8 + i) * R + bn + tx*8 + j] = acc[i][j] + bias[bn + tx*8 + j];
}

// ---------------- software grid barrier (monotonic counter) ----------------
__device__ __forceinline__ void gridbar(unsigned target) {
    __syncthreads();
    __threadfence();
    if (threadIdx.x == 0) {
        atomicAdd(&g_barcnt, 1u);
        unsigned v;
        do {
            asm volatile("ld.acquire.gpu.b32 %0, [%1];"
                         : "=r"(v) : "l"(&g_barcnt) : "memory");
            if (v < target) __nanosleep(64);
        } while (v < target);
    }
    __syncthreads();
}

// ---------------- persistent fused scan: 256 x (sparse GEMM + LIF) ----------------
// 1024 blocks x 128 threads, guaranteed co-resident via __launch_bounds__(128,7).
// Per step: phase S (same tiles/chains as round-11 stepS_k), grid barrier,
// phase B (1 element per thread, same reduction order), grid barrier.
__global__ void __launch_bounds__(128, 7) scan_k() {
    __shared__ __align__(8) unsigned short ssh[CHR * SSTRIDE];    // 5 KB
    __shared__ int ssum;
    int tid = threadIdx.x;
    int bx  = blockIdx.x;
    int ct    = bx & 15;          // col tile
    int bg    = (bx >> 4) & 3;    // batch group
    int chunk = bx >> 6;          // row chunk
    int col = ct * 128 + tid;
    int i0  = chunk * CHR;

    int gid = bx * 128 + tid;     // 0..131071 — phase B element
    int b = gid >> 11;
    int j = gid & (R - 1);

    int cnt = g_cnt[chunk * R + col];
    const uint2* p = &g_ent[(size_t)chunk * MAXNZ * R + col];

    unsigned bar = 0;
    for (int t = 0; t < T_STEPS; t++) {
        // ---- phase S: load spike tile (128 rows x 16 batches) ----
        for (int e2 = tid; e2 < CHR * 4; e2 += 128) {
            int i = e2 >> 2, q = e2 & 3;
            *reinterpret_cast<uint2*>(&ssh[i * SSTRIDE + q * 4]) =
                *reinterpret_cast<const uint2*>(&g_St16[(size_t)(i0 + i) * BATCH + bg * 16 + q * 4]);
        }
        __syncthreads();

        float acc[16];
        #pragma unroll
        for (int bb = 0; bb < 16; bb++) acc[bb] = 0.0f;

        #pragma unroll 2
        for (int rank = 0; rank < cnt; rank++) {
            uint2 e = p[(size_t)rank * R];
            float w = __uint_as_float(e.x);
            int r = (int)e.y;
            const unsigned short* row = &ssh[r * SSTRIDE];
            uint2 q0 = *reinterpret_cast<const uint2*>(row + 0);
            uint2 q1 = *reinterpret_cast<const uint2*>(row + 4);
            uint2 q2 = *reinterpret_cast<const uint2*>(row + 8);
            uint2 q3 = *reinterpret_cast<const uint2*>(row + 12);
            acc[0]  += w * __uint_as_float(q0.x << 16);
            acc[1]  += w * __uint_as_float(q0.x & 0xffff0000u);
            acc[2]  += w * __uint_as_float(q0.y << 16);
            acc[3]  += w * __uint_as_float(q0.y & 0xffff0000u);
            acc[4]  += w * __uint_as_float(q1.x << 16);
            acc[5]  += w * __uint_as_float(q1.x & 0xffff0000u);
            acc[6]  += w * __uint_as_float(q1.y << 16);
            acc[7]  += w * __uint_as_float(q1.y & 0xffff0000u);
            acc[8]  += w * __uint_as_float(q2.x << 16);
            acc[9]  += w * __uint_as_float(q2.x & 0xffff0000u);
            acc[10] += w * __uint_as_float(q2.y << 16);
            acc[11] += w * __uint_as_float(q2.y & 0xffff0000u);
            acc[12] += w * __uint_as_float(q3.x << 16);
            acc[13] += w * __uint_as_float(q3.x & 0xffff0000u);
            acc[14] += w * __uint_as_float(q3.y << 16);
            acc[15] += w * __uint_as_float(q3.y & 0xffff0000u);
        }

        #pragma unroll
        for (int bb = 0; bb < 16; bb++)
            g_part[((size_t)chunk * BATCH + bg * 16 + bb) * R + col] = acc[bb];

        bar += NBLK; gridbar(bar);

        // ---- phase B: reduce + LIF + spike (1 element per thread) ----
        if (tid == 0) ssum = 0;
        __syncthreads();

        float sum = g_drive[((size_t)t * BATCH + b) * R + j];
        #pragma unroll
        for (int ks = 0; ks < NCH; ks++)
            sum += g_part[((size_t)ks * BATCH + b) * R + j];

        float V = BETA * g_V[gid] + sum;
        float s = (V > 1.0f) ? 1.0f : 0.0f;
        V -= s;
        g_V[gid] = V;
        g_St16[(size_t)j * BATCH + b] = (s != 0.0f) ? (unsigned short)0x3F80 : (unsigned short)0;

        unsigned ballot = __ballot_sync(0xffffffffu, s != 0.0f);
        if ((tid & 31) == 0) {
            g_bits[((size_t)t * BATCH + b) * (R / 32) + (j >> 5)] = ballot;
            atomicAdd(&ssum, __popc(ballot));
        }
        __syncthreads();
        if (tid == 0) atomicAdd(&g_spk, (unsigned long long)ssum);

        bar += NBLK; gridbar(bar);
    }
}

// ---------------- logits for all (t,b) from spike bitmasks ----------------
__global__ void __launch_bounds__(128) logits_k(const float* __restrict__ wh,
                                                const float* __restrict__ bh,
                                                float* __restrict__ out) {
    int tb = blockIdx.x;      // t*64 + b
    int d = threadIdx.x;
    __shared__ unsigned bits[64];
    if (d < 64) bits[d] = g_bits[(size_t)tb * 64 + d];
    __syncthreads();
    float acc = bh[d];
    #pragma unroll 1
    for (int w = 0; w < 64; w++) {
        unsigned m = bits[w];
        while (m) {                 // uniform across warp (m from shared)
            int k = __ffs(m) - 1;
            m &= m - 1;
            acc += wh[(size_t)(w * 32 + k) * DOUT + d];
        }
    }
    out[(size_t)tb * DOUT + d] = acc;
}

// ---------------- readout = mean over T ----------------
__global__ void readout_k(const float* __restrict__ logits, float* __restrict__ out) {
    int idx = blockIdx.x * 256 + threadIdx.x;   // 0..8191
    if (idx < BATCH * DOUT) {
        float s = 0.f;
        for (int t = 0; t < T_STEPS; t++) s += logits[(size_t)t * BATCH * DOUT + idx];
        out[idx] = s * (1.0f / T_STEPS);
    }
}

__global__ void scalars_k(float* __restrict__ out) {
    out[0] = (float)((double)g_spk / (double)((size_t)T_STEPS * BATCH * R)); // spike_rate
    out[1] = g_active_ratio;                                                 // active_ratio
}

// ---------------- launch ----------------
extern "C" void kernel_launch(void* const* d_in, const int* in_sizes, int n_in,
                              void* d_out, int out_size) {
    const float* x      = (const float*)d_in[0];
    const float* w_in   = (const float*)d_in[1];
    const float* b_in   = (const float*)d_in[2];
    const float* w_rec  = (const float*)d_in[3];
    const float* w_head = (const float*)d_in[4];
    const float* b_head = (const float*)d_in[5];
    float* out = (float*)d_out;

    void *h1p, *h2p, *vp, *stp, *spkp, *barp;
    cudaGetSymbolAddress(&h1p,  g_hist1);
    cudaGetSymbolAddress(&h2p,  g_hist2);
    cudaGetSymbolAddress(&vp,   g_V);
    cudaGetSymbolAddress(&stp,  g_St16);
    cudaGetSymbolAddress(&spkp, g_spk);
    cudaGetSymbolAddress(&barp, g_barcnt);

    cudaMemsetAsync(h1p,  0, 65536 * sizeof(unsigned));
    cudaMemsetAsync(h2p,  0, 65536 * sizeof(unsigned));
    cudaMemsetAsync(vp,   0, BATCH * R * sizeof(float));
    cudaMemsetAsync(stp,  0, R * BATCH * sizeof(unsigned short));
    cudaMemsetAsync(spkp, 0, sizeof(unsigned long long));
    cudaMemsetAsync(barp, 0, sizeof(unsigned));

    // exact top-k threshold
    hist1_k<<<2048, 512>>>(w_rec);
    sel1_k<<<1, 1024>>>();
    hist2_k<<<2048, 512>>>(w_rec);
    sel2_k<<<1, 1024>>>();

    // build sparse W_eff structure (static across the whole scan)
    build_k<<<(NCH * R) / 128, 128>>>(w_rec);

    // input projection
    drive_k<<<dim3(R / BN2, (T_STEPS * BATCH) / BM2), 256>>>(x, w_in, b_in);

    // fused persistent LIF scan (bitwise == split round-11 version)
    scan_k<<<NBLK, 128>>>();

    // outputs: [readout 8192][logits_seq 2097152][spike_rate 1][active_ratio 1]
    float* logits_out = out + BATCH * DOUT;
    logits_k<<<T_STEPS * BATCH, 128>>>(w_head, b_head, logits_out);
    readout_k<<<(BATCH * DOUT + 255) / 256, 256>>>(logits_out, out);
    scalars_k<<<1, 1>>>(out + BATCH * DOUT + (size_t)T_STEPS * BATCH * DOUT);
}